// round 10
// baseline (speedup 1.0000x reference)
#include <cuda_runtime.h>
#include <math.h>

// ---------------------------------------------------------------------------
// SinkhornLoss: m=8, n=2048, d=3, eps=1e-3, 50 iters, early-stop flag.
// chain(i,k) = 2c*x_i.y_k + qb_k, qb_k = c*pot_k - c*||col_k||^2, c=log2e/eps.
// R9 layout: warp-complete rows (4 rows x all 2048 cols per warp; no SMEM, no
// block barrier) + SoA column-PAIR storage: A={c0lo,c0hi,c1lo,c1hi},
// B={c2lo,c2hi,qblo,qbhi} so two LDG.128 give FFMA2 operands as aligned pairs
// (zero packing MOVs in the hot loop). Row coords duplicated into pairs once.
// ---------------------------------------------------------------------------

#define MB     8
#define NB     2048
#define EPSF   1e-3f
#define THRESH 1e-3f
#define NITERS 50
#define CSC    1442.6950408889634f      // log2(e)/eps
#define INVC   6.931471805599453e-4f    // 1/CSC = eps*ln2

#define RPW    4                         // rows per warp (warp-complete)
#define WPB    2                         // warps per block
#define THREADS (WPB * 32)
#define ROWSB  (WPB * RPW)               // 8 rows per block
#define TPW    (NB / 64)                 // 32 tiles (64 cols each) per warp
#define RGPB   (NB / ROWSB)              // 256 row-groups per batch
#define GRID_HALF (MB * RGPB)            // 2048 blocks

typedef unsigned long long u64;

// Scratch (allocation-free rule: __device__ globals)
__device__ float4   g_cx[MB * NB];      // {x0,x1,x2, c*u - c*||x||^2} (AoS, rows + k_loss)
__device__ float4   g_cy[MB * NB];      // {y0,y1,y2, c*v - c*||y||^2}
__device__ float4   g_xa[MB * NB / 2];  // x-side col pairs {c0lo,c0hi,c1lo,c1hi}
__device__ float4   g_xb[MB * NB / 2];  // x-side col pairs {c2lo,c2hi,qblo,qbhi}
__device__ float4   g_ya[MB * NB / 2];  // y-side col pairs
__device__ float4   g_yb[MB * NB / 2];
__device__ float    g_n2x[MB * NB];     // c*||x||^2 (exact)
__device__ float    g_n2y[MB * NB];
__device__ float    g_u[MB * NB];
__device__ float    g_v[MB * NB];
__device__ float    g_la[MB * NB];
__device__ float    g_lb[MB * NB];
__device__ unsigned g_err[NITERS];      // per-iter max(err_u, err_v), float bits

__device__ __forceinline__ float ex2f(float x) {
    float r; asm("ex2.approx.ftz.f32 %0, %1;" : "=f"(r) : "f"(x)); return r;
}
__device__ __forceinline__ u64 pack2(float lo, float hi) {
    u64 r; asm("mov.b64 %0, {%1, %2};" : "=l"(r) : "f"(lo), "f"(hi)); return r;
}
__device__ __forceinline__ float lo2(u64 p) {
    float l, h; asm("mov.b64 {%0, %1}, %2;" : "=f"(l), "=f"(h) : "l"(p)); return l;
}
__device__ __forceinline__ float hi2(u64 p) {
    float l, h; asm("mov.b64 {%0, %1}, %2;" : "=f"(l), "=f"(h) : "l"(p)); return h;
}
__device__ __forceinline__ u64 fma2(u64 a, u64 b, u64 c) {
    u64 d; asm("fma.rn.f32x2 %0, %1, %2, %3;" : "=l"(d) : "l"(a), "l"(b), "l"(c)); return d;
}
__device__ __forceinline__ u64 add2(u64 a, u64 b) {
    u64 d; asm("add.rn.f32x2 %0, %1, %2;" : "=l"(d) : "l"(a), "l"(b)); return d;
}

// ---------------------------------------------------------------------------
__global__ void k_init(const float* __restrict__ px, const float* __restrict__ py,
                       const float* __restrict__ a, const float* __restrict__ b,
                       float* __restrict__ out) {
    int i = blockIdx.x * blockDim.x + threadIdx.x;
    if (i < MB * NB) {
        int p = i >> 1, c = i & 1;
        float x0 = px[3 * i], x1 = px[3 * i + 1], x2 = px[3 * i + 2];
        float n2x = CSC * (x0 * x0 + x1 * x1 + x2 * x2);
        g_cx[i] = make_float4(x0, x1, x2, -n2x);     // u = 0
        g_n2x[i] = n2x;
        ((float*)&g_xa[p])[c]     = x0;
        ((float*)&g_xa[p])[2 + c] = x1;
        ((float*)&g_xb[p])[c]     = x2;
        ((float*)&g_xb[p])[2 + c] = -n2x;
        float y0 = py[3 * i], y1 = py[3 * i + 1], y2 = py[3 * i + 2];
        float n2y = CSC * (y0 * y0 + y1 * y1 + y2 * y2);
        g_cy[i] = make_float4(y0, y1, y2, -n2y);     // v = 0
        g_n2y[i] = n2y;
        ((float*)&g_ya[p])[c]     = y0;
        ((float*)&g_ya[p])[2 + c] = y1;
        ((float*)&g_yb[p])[c]     = y2;
        ((float*)&g_yb[p])[2 + c] = -n2y;
        g_u[i] = 0.0f;
        g_v[i] = 0.0f;
        g_la[i] = logf(a[i]);
        g_lb[i] = logf(b[i]);
    }
    if (i < NITERS) g_err[i] = 0u;
    if (i < MB)     out[i] = 0.0f;
}

// ---------------------------------------------------------------------------
// One half Sinkhorn update. SIDE=0 updates u (rows=x, cols=y+v);
//                           SIDE=1 updates v (rows=y, cols=x+u).
// Freeze semantics: once g_err[s] < THRESH, later iterations never write
// g_err (so it stays 0 < THRESH) and never update potentials — matches the
// reference's sticky done flag.
template <int SIDE>
__global__ void __launch_bounds__(THREADS, 14) k_half(int iter) {
    if (iter > 0 && __uint_as_float(g_err[iter - 1]) < THRESH) return;

    const int warp  = threadIdx.x >> 5;
    const int lane  = threadIdx.x & 31;
    const int batch = blockIdx.x / RGPB;
    const int row0  = (blockIdx.x % RGPB) * ROWSB + warp * RPW;
    const int base  = batch * NB;

    const float4* __restrict__ rp  = SIDE ? g_cy : g_cx;   // row-side coords (AoS)
    const float4* __restrict__ ca  = SIDE ? g_xa : g_ya;   // col pairs {c0,c1}
    const float4* __restrict__ cb  = SIDE ? g_xb : g_yb;   // col pairs {c2,qb}
    float4*                    rwA = SIDE ? g_cy : g_cx;   // row-side AoS qb write
    float4*                    rwB = SIDE ? g_yb : g_xb;   // row-side SoA qb write
    const float*  __restrict__ n2  = SIDE ? g_n2y : g_n2x; // c*||row||^2
    float*                     upd = SIDE ? g_v : g_u;     // potential being updated
    const float*  __restrict__ rl  = SIDE ? g_lb : g_la;   // row-side log marginal

    // Row coords, each duplicated into an f32x2 pair (loop-invariant)
    u64 rx[RPW], ry[RPW], rz[RPW];
    float mxs[RPW];
#pragma unroll
    for (int j = 0; j < RPW; j++) {
        float4 R = rp[base + row0 + j];
        float v0 = R.x * (2.0f * CSC), v1 = R.y * (2.0f * CSC), v2 = R.z * (2.0f * CSC);
        rx[j] = pack2(v0, v0);
        ry[j] = pack2(v1, v1);
        rz[j] = pack2(v2, v2);
        mxs[j] = -3.4e38f;
    }
    const float4* cap = ca + (base >> 1) + lane;   // lane's col pair in tile 0
    const float4* cbp = cb + (base >> 1) + lane;

    // ---- Pass 1: row max of chain = 2c*row.col + qb (pairs of columns)
#pragma unroll 4
    for (int t = 0; t < TPW; t++) {
        float4 A = cap[t * 32];            // {c0lo,c0hi, c1lo,c1hi}
        float4 B = cbp[t * 32];            // {c2lo,c2hi, qblo,qbhi}
        u64 c0 = pack2(A.x, A.y), c1 = pack2(A.z, A.w);
        u64 c2 = pack2(B.x, B.y), qq = pack2(B.z, B.w);
#pragma unroll
        for (int j = 0; j < RPW; j++) {
            u64 s2 = fma2(rx[j], c0, fma2(ry[j], c1, fma2(rz[j], c2, qq)));
            mxs[j] = fmaxf(mxs[j], fmaxf(lo2(s2), hi2(s2)));
        }
    }
#pragma unroll
    for (int j = 0; j < RPW; j++) {
#pragma unroll
        for (int o = 16; o; o >>= 1)
            mxs[j] = fmaxf(mxs[j], __shfl_xor_sync(0xffffffffu, mxs[j], o));
    }
    u64 nmx[RPW];
#pragma unroll
    for (int j = 0; j < RPW; j++) nmx[j] = pack2(-mxs[j], -mxs[j]);

    // ---- Pass 2: row sum of ex2(chain - mx) (same chain bits => arg <= 0)
    float sA[RPW], sB[RPW];
#pragma unroll
    for (int j = 0; j < RPW; j++) { sA[j] = 0.0f; sB[j] = 0.0f; }

#pragma unroll 4
    for (int t = 0; t < TPW; t++) {
        float4 A = cap[t * 32];
        float4 B = cbp[t * 32];
        u64 c0 = pack2(A.x, A.y), c1 = pack2(A.z, A.w);
        u64 c2 = pack2(B.x, B.y), qq = pack2(B.z, B.w);
#pragma unroll
        for (int j = 0; j < RPW; j++) {
            u64 s2 = fma2(rx[j], c0, fma2(ry[j], c1, fma2(rz[j], c2, qq)));
            u64 a2 = add2(s2, nmx[j]);
            sA[j] += ex2f(lo2(a2));
            sB[j] += ex2f(hi2(a2));
        }
    }
    float sm[RPW];
#pragma unroll
    for (int j = 0; j < RPW; j++) {
        sm[j] = sA[j] + sB[j];
#pragma unroll
        for (int o = 16; o; o >>= 1)
            sm[j] += __shfl_xor_sync(0xffffffffu, sm[j], o);
    }

    // ---- Finalize: lane 0 of each warp handles its 4 rows (warp-local)
    if (lane == 0) {
        float e = 0.0f;
#pragma unroll
        for (int j = 0; j < RPW; j++) {
            int r = base + row0 + j;
            float n2r = n2[r];                       // c*||row||^2 (exact)
            float mx_row = (mxs[j] - n2r) * INVC;    // true max of (pot - M)
            float nv = EPSF * rl[r] - mx_row - EPSF * __logf(sm[j]);
            float ov = upd[r];
            upd[r] = nv;
            float qb = fmaf(CSC, nv, -n2r);          // c*pot_new - c*||row||^2
            ((float*)(rwA + r))[3] = qb;             // AoS (row reads + k_loss)
            ((float*)&rwB[r >> 1])[2 + (r & 1)] = qb;// SoA pair (hot loop)
            e = fmaxf(e, fabsf(nv - ov));
        }
        atomicMax(&g_err[iter], __float_as_uint(e)); // e>=0: uint order==float order
    }
}

// ---------------------------------------------------------------------------
// loss[b] = sum_{i,k} M * exp((u_i + v_k - M)/eps)   (R4-style, AoS)
#define LROWS 8
#define LCPW  (NB / WPB)
#define LTPW  (LCPW / 32)
__global__ void __launch_bounds__(THREADS, 14) k_loss(float* __restrict__ out) {
    const int warp  = threadIdx.x >> 5;
    const int lane  = threadIdx.x & 31;
    const int batch = blockIdx.x / (NB / LROWS);
    const int row0  = (blockIdx.x % (NB / LROWS)) * LROWS;
    const int base  = batch * NB;

    float cx[LROWS], cy[LROWS], cz[LROWS], aj[LROWS], U[LROWS];
#pragma unroll
    for (int j = 0; j < LROWS; j++) {
        float4 R = g_cx[base + row0 + j];            // {x, c*u - c*x2}
        cx[j] = R.x * (2.0f * CSC);
        cy[j] = R.y * (2.0f * CSC);
        cz[j] = R.z * (2.0f * CSC);
        aj[j] = R.w;
        U[j]  = g_u[base + row0 + j];
    }
    const int kbeg = base + warp * LCPW + lane;

    float tot = 0.0f;
#pragma unroll 2
    for (int t = 0; t < LTPW; t++) {
        int k = kbeg + t * 32;
        float4 C = g_cy[k];                          // {y, c*v - c*y2}
        float vk = g_v[k];
#pragma unroll
        for (int j = 0; j < LROWS; j++) {
            float carg = fmaf(cx[j], C.x, fmaf(cy[j], C.y, fmaf(cz[j], C.z, C.w + aj[j])));
            float e  = ex2f(carg);                   // = P weight (scaled)
            float uv = U[j] + vk;
            float Mv = fmaf(carg, -INVC, uv);        // = M (unclamped)
            tot = fmaf(Mv, e, tot);
        }
    }
#pragma unroll
    for (int o = 16; o; o >>= 1)
        tot += __shfl_xor_sync(0xffffffffu, tot, o);
    if (lane == 0) atomicAdd(&out[batch], tot);
}

// ---------------------------------------------------------------------------
extern "C" void kernel_launch(void* const* d_in, const int* in_sizes, int n_in,
                              void* d_out, int out_size) {
    (void)in_sizes; (void)n_in; (void)out_size;
    const float* px = (const float*)d_in[0];   // predicted [8,2048,3]
    const float* py = (const float*)d_in[1];   // expected  [8,2048,3]
    const float* a  = (const float*)d_in[2];   // [8,2048]
    const float* b  = (const float*)d_in[3];   // [8,2048]
    float* out = (float*)d_out;                // [8]

    k_init<<<(MB * NB + 255) / 256, 256>>>(px, py, a, b, out);
    for (int t = 0; t < NITERS; t++) {
        k_half<0><<<GRID_HALF, THREADS>>>(t);
        k_half<1><<<GRID_HALF, THREADS>>>(t);
    }
    k_loss<<<GRID_HALF, THREADS>>>(out);
}

// round 11
// speedup vs baseline: 2.5182x; 2.5182x over previous
#include <cuda_runtime.h>
#include <math.h>

// ---------------------------------------------------------------------------
// SinkhornLoss: m=8, n=2048, d=3, eps=1e-3, 50 iters, early-stop flag.
// chain(i,k) = 2c*x_i.y_k + qb_k, qb_k = c*pot_k - c*||col_k||^2, c=log2e/eps.
// R10: ADAPTIVE ONE-PASS LSE. Per-row shift = previous iteration's true chain
// max (g_shx/g_shy). Fused pass computes sum of ex2(chain - shift) AND the
// true arg-max; if arg-max in [-90, +110] the sum is valid (lse = shift +
// log2 sum). Otherwise a corrective pass recomputes with the exact max
// (always the case on iteration 0, shift=0). Base structure = R4 (best).
// ---------------------------------------------------------------------------

#define MB     8
#define NB     2048
#define EPSF   1e-3f
#define THRESH 1e-3f
#define NITERS 50
#define CSC    1442.6950408889634f      // log2(e)/eps
#define INVC   6.931471805599453e-4f    // 1/CSC = eps*ln2
#define REDO_HI 110.0f                  // overflow bound (terms <= 2^110)
#define REDO_LO (-90.0f)                // FTZ-flush bound

#define ROWS   8                         // rows per block (4 f32x2 pairs)
#define PAIRS  (ROWS / 2)
#define WPB    2                         // warps per block (column split)
#define THREADS (WPB * 32)
#define CPW    (NB / WPB)                // 1024 columns per warp
#define TPW    (CPW / 32)                // 32 tile iters per warp
#define RGPB   (NB / ROWS)               // 256 row-groups per batch
#define GRID_HALF (MB * RGPB)            // 2048 blocks

typedef unsigned long long u64;

// Scratch (allocation-free rule: __device__ globals)
__device__ float4   g_cx[MB * NB];  // {x0,x1,x2, c*u - c*||x||^2}
__device__ float4   g_cy[MB * NB];  // {y0,y1,y2, c*v - c*||y||^2}
__device__ float    g_n2x[MB * NB]; // c*||x||^2 (exact, no drift)
__device__ float    g_n2y[MB * NB]; // c*||y||^2
__device__ float    g_shx[MB * NB]; // per-row chain-max shift (u-update rows)
__device__ float    g_shy[MB * NB]; // per-row chain-max shift (v-update rows)
__device__ float    g_u[MB * NB];
__device__ float    g_v[MB * NB];
__device__ float    g_la[MB * NB];
__device__ float    g_lb[MB * NB];
__device__ unsigned g_err[NITERS];  // per-iter max(err_u, err_v), float bits

__device__ __forceinline__ float ex2f(float x) {
    float r; asm("ex2.approx.ftz.f32 %0, %1;" : "=f"(r) : "f"(x)); return r;
}
__device__ __forceinline__ u64 pack2(float lo, float hi) {
    u64 r; asm("mov.b64 %0, {%1, %2};" : "=l"(r) : "f"(lo), "f"(hi)); return r;
}
__device__ __forceinline__ float lo2(u64 p) {
    float l, h; asm("mov.b64 {%0, %1}, %2;" : "=f"(l), "=f"(h) : "l"(p)); return l;
}
__device__ __forceinline__ float hi2(u64 p) {
    float l, h; asm("mov.b64 {%0, %1}, %2;" : "=f"(l), "=f"(h) : "l"(p)); return h;
}
__device__ __forceinline__ u64 fma2(u64 a, u64 b, u64 c) {
    u64 d; asm("fma.rn.f32x2 %0, %1, %2, %3;" : "=l"(d) : "l"(a), "l"(b), "l"(c)); return d;
}
__device__ __forceinline__ u64 add2(u64 a, u64 b) {
    u64 d; asm("add.rn.f32x2 %0, %1, %2;" : "=l"(d) : "l"(a), "l"(b)); return d;
}

// ---------------------------------------------------------------------------
__global__ void k_init(const float* __restrict__ px, const float* __restrict__ py,
                       const float* __restrict__ a, const float* __restrict__ b,
                       float* __restrict__ out) {
    int i = blockIdx.x * blockDim.x + threadIdx.x;
    if (i < MB * NB) {
        float x0 = px[3 * i], x1 = px[3 * i + 1], x2 = px[3 * i + 2];
        float n2x = CSC * (x0 * x0 + x1 * x1 + x2 * x2);
        g_cx[i] = make_float4(x0, x1, x2, -n2x);     // u = 0
        g_n2x[i] = n2x;
        float y0 = py[3 * i], y1 = py[3 * i + 1], y2 = py[3 * i + 2];
        float n2y = CSC * (y0 * y0 + y1 * y1 + y2 * y2);
        g_cy[i] = make_float4(y0, y1, y2, -n2y);     // v = 0
        g_n2y[i] = n2y;
        g_shx[i] = 0.0f;     // exact "stale" shift: iter 0 always redoes cleanly
        g_shy[i] = 0.0f;
        g_u[i] = 0.0f;
        g_v[i] = 0.0f;
        g_la[i] = logf(a[i]);
        g_lb[i] = logf(b[i]);
    }
    if (i < NITERS) g_err[i] = 0u;
    if (i < MB)     out[i] = 0.0f;
}

// ---------------------------------------------------------------------------
// One half Sinkhorn update. SIDE=0 updates u (rows=x, cols=y+v);
//                           SIDE=1 updates v (rows=y, cols=x+u).
// Freeze: once g_err[s] < THRESH, later launches return untouched (g_err
// slots stay 0 < THRESH -> sticky), matching the reference's done flag.
template <int SIDE>
__global__ void __launch_bounds__(THREADS, 14) k_half(int iter) {
    if (iter > 0 && __uint_as_float(g_err[iter - 1]) < THRESH) return;

    __shared__ float s_mx[WPB][ROWS];
    __shared__ float s_sm[WPB][ROWS];

    const int warp  = threadIdx.x >> 5;
    const int lane  = threadIdx.x & 31;
    const int batch = blockIdx.x / RGPB;
    const int row0  = (blockIdx.x % RGPB) * ROWS;
    const int base  = batch * NB;

    const float4* __restrict__ rp  = SIDE ? g_cy : g_cx;   // row-side coords
    const float4* __restrict__ cp  = SIDE ? g_cx : g_cy;   // col-side {coords, qb}
    float4*                    rw  = SIDE ? g_cy : g_cx;   // row-side (finalize .w write)
    const float*  __restrict__ n2  = SIDE ? g_n2y : g_n2x; // c*||row||^2
    float*                     shp = SIDE ? g_shy : g_shx; // per-row shift (read+write)
    float*                     upd = SIDE ? g_v : g_u;     // potential being updated
    const float*  __restrict__ rl  = SIDE ? g_lb : g_la;   // row-side log marginal

    // Row-pair packed coordinates (pre-scaled by 2c) and packed -shift
    u64 cx2[PAIRS], cy2[PAIRS], cz2[PAIRS], nsh2[PAIRS];
    float mxs[ROWS], sm[ROWS];
#pragma unroll
    for (int p = 0; p < PAIRS; p++) {
        float4 R0 = rp[base + row0 + 2 * p];
        float4 R1 = rp[base + row0 + 2 * p + 1];
        cx2[p] = pack2(R0.x * (2.0f * CSC), R1.x * (2.0f * CSC));
        cy2[p] = pack2(R0.y * (2.0f * CSC), R1.y * (2.0f * CSC));
        cz2[p] = pack2(R0.z * (2.0f * CSC), R1.z * (2.0f * CSC));
        nsh2[p] = pack2(-shp[base + row0 + 2 * p], -shp[base + row0 + 2 * p + 1]);
    }
#pragma unroll
    for (int j = 0; j < ROWS; j++) { mxs[j] = -3.4e38f; sm[j] = 0.0f; }
    const int kbeg = base + warp * CPW + lane;

    // ---- Fused pass: arg = chain - shift; track max(arg) and sum ex2(arg)
#pragma unroll 2
    for (int t = 0; t < TPW; t++) {
        int k = kbeg + t * 32;
        float4 C = cp[k];                        // {c0,c1,c2, qb}
        u64 Cx = pack2(C.x, C.x), Cy = pack2(C.y, C.y), Cz = pack2(C.z, C.z);
        u64 Q  = pack2(C.w, C.w);
#pragma unroll
        for (int p = 0; p < PAIRS; p++) {
            u64 s2 = fma2(cx2[p], Cx, fma2(cy2[p], Cy, fma2(cz2[p], Cz, Q)));
            u64 a2 = add2(s2, nsh2[p]);
            float alo = lo2(a2), ahi = hi2(a2);
            mxs[2 * p]     = fmaxf(mxs[2 * p],     alo);
            mxs[2 * p + 1] = fmaxf(mxs[2 * p + 1], ahi);
            sm[2 * p]     += ex2f(alo);
            sm[2 * p + 1] += ex2f(ahi);
        }
    }
#pragma unroll
    for (int j = 0; j < ROWS; j++) {
#pragma unroll
        for (int o = 16; o; o >>= 1) {
            mxs[j] = fmaxf(mxs[j], __shfl_xor_sync(0xffffffffu, mxs[j], o));
            sm[j] += __shfl_xor_sync(0xffffffffu, sm[j], o);
        }
    }
    if (lane == 0) {
#pragma unroll
        for (int j = 0; j < ROWS; j++) { s_mx[warp][j] = mxs[j]; s_sm[warp][j] = sm[j]; }
    }
    __syncthreads();

    // Combined arg-max per row; block-uniform redo decision
    float amax[ROWS];
    bool redo = false;
#pragma unroll
    for (int j = 0; j < ROWS; j++) {
        amax[j] = fmaxf(s_mx[0][j], s_mx[1][j]);
        redo = redo || (amax[j] > REDO_HI) || (amax[j] < REDO_LO);
    }

    if (redo) {
        // Corrective pass with exact shift: chain max = old_shift + amax
        u64 nmx2[PAIRS];
#pragma unroll
        for (int p = 0; p < PAIRS; p++) {
            float sh0 = -lo2(nsh2[p]), sh1 = -hi2(nsh2[p]);
            nmx2[p] = pack2(-(sh0 + amax[2 * p]), -(sh1 + amax[2 * p + 1]));
        }
#pragma unroll
        for (int j = 0; j < ROWS; j++) sm[j] = 0.0f;
#pragma unroll 2
        for (int t = 0; t < TPW; t++) {
            int k = kbeg + t * 32;
            float4 C = cp[k];
            u64 Cx = pack2(C.x, C.x), Cy = pack2(C.y, C.y), Cz = pack2(C.z, C.z);
            u64 Q  = pack2(C.w, C.w);
#pragma unroll
            for (int p = 0; p < PAIRS; p++) {
                u64 s2 = fma2(cx2[p], Cx, fma2(cy2[p], Cy, fma2(cz2[p], Cz, Q)));
                u64 a2 = add2(s2, nmx2[p]);
                sm[2 * p]     += ex2f(lo2(a2));
                sm[2 * p + 1] += ex2f(hi2(a2));
            }
        }
#pragma unroll
        for (int j = 0; j < ROWS; j++) {
#pragma unroll
            for (int o = 16; o; o >>= 1)
                sm[j] += __shfl_xor_sync(0xffffffffu, sm[j], o);
        }
        if (lane == 0) {
#pragma unroll
            for (int j = 0; j < ROWS; j++) s_sm[warp][j] = sm[j];
        }
        __syncthreads();
    }

    // ---- Finalize: warp 0, lanes 0..7 each own one row
    if (warp == 0 && lane < ROWS) {
        int r = base + row0 + lane;
        float smv = s_sm[0][lane] + s_sm[1][lane];
        float amx = fmaxf(s_mx[0][lane], s_mx[1][lane]);   // arg max (rel. old shift)
        float shold = shp[r];
        float mxc = shold + amx;                            // true chain max
        float shift_used = redo ? mxc : shold;
        float n2r = n2[r];                                  // c*||row||^2 (exact)
        float nv = EPSF * rl[r] - (shift_used - n2r) * INVC - EPSF * __logf(smv);
        float ov = upd[r];
        upd[r] = nv;
        shp[r] = mxc;                                       // shift for next iteration
        // refresh this row's column-side qb: c*pot_new - c*||row||^2
        ((float*)(rw + r))[3] = fmaf(CSC, nv, -n2r);
        float e = fabsf(nv - ov);
#pragma unroll
        for (int o = 4; o; o >>= 1)
            e = fmaxf(e, __shfl_xor_sync(0x000000ffu, e, o));
        if (lane == 0)
            atomicMax(&g_err[iter], __float_as_uint(e));    // e>=0: uint order==float order
    }
}

// ---------------------------------------------------------------------------
// loss[b] = sum_{i,k} M * exp((u_i + v_k - M)/eps)
__global__ void __launch_bounds__(THREADS, 14) k_loss(float* __restrict__ out) {
    const int warp  = threadIdx.x >> 5;
    const int lane  = threadIdx.x & 31;
    const int batch = blockIdx.x / RGPB;
    const int row0  = (blockIdx.x % RGPB) * ROWS;
    const int base  = batch * NB;

    float cx[ROWS], cy[ROWS], cz[ROWS], aj[ROWS], U[ROWS];
#pragma unroll
    for (int j = 0; j < ROWS; j++) {
        float4 R = g_cx[base + row0 + j];            // {x, c*u - c*x2}
        cx[j] = R.x * (2.0f * CSC);
        cy[j] = R.y * (2.0f * CSC);
        cz[j] = R.z * (2.0f * CSC);
        aj[j] = R.w;
        U[j]  = g_u[base + row0 + j];
    }
    const int kbeg = base + warp * CPW + lane;

    float tot = 0.0f;
#pragma unroll 2
    for (int t = 0; t < TPW; t++) {
        int k = kbeg + t * 32;
        float4 C = g_cy[k];                          // {y, c*v - c*y2}
        float vk = g_v[k];
#pragma unroll
        for (int j = 0; j < ROWS; j++) {
            float carg = fmaf(cx[j], C.x, fmaf(cy[j], C.y, fmaf(cz[j], C.z, C.w + aj[j])));
            float e  = ex2f(carg);
            float uv = U[j] + vk;
            float Mv = fmaf(carg, -INVC, uv);        // = M (unclamped)
            tot = fmaf(Mv, e, tot);
        }
    }
#pragma unroll
    for (int o = 16; o; o >>= 1)
        tot += __shfl_xor_sync(0xffffffffu, tot, o);
    if (lane == 0) atomicAdd(&out[batch], tot);
}

// ---------------------------------------------------------------------------
extern "C" void kernel_launch(void* const* d_in, const int* in_sizes, int n_in,
                              void* d_out, int out_size) {
    (void)in_sizes; (void)n_in; (void)out_size;
    const float* px = (const float*)d_in[0];   // predicted [8,2048,3]
    const float* py = (const float*)d_in[1];   // expected  [8,2048,3]
    const float* a  = (const float*)d_in[2];   // [8,2048]
    const float* b  = (const float*)d_in[3];   // [8,2048]
    float* out = (float*)d_out;                // [8]

    k_init<<<(MB * NB + 255) / 256, 256>>>(px, py, a, b, out);
    for (int t = 0; t < NITERS; t++) {
        k_half<0><<<GRID_HALF, THREADS>>>(t);
        k_half<1><<<GRID_HALF, THREADS>>>(t);
    }
    k_loss<<<GRID_HALF, THREADS>>>(out);
}

// round 12
// speedup vs baseline: 2.8142x; 1.1175x over previous
#include <cuda_runtime.h>
#include <math.h>

// ---------------------------------------------------------------------------
// SinkhornLoss: m=8, n=2048, d=3, eps=1e-3, 50 iters, early-stop flag.
// chain(i,k) = 2c*x_i.y_k + qb_k, qb_k = c*pot_k - c*||col_k||^2, c=log2e/eps.
// R11: one-pass LSE with SUM-BASED validity (no max tracking): compute
// smv = sum ex2(chain - shift_pred); valid iff smv in [2^-90, +inf). On
// failure, classic two-pass (exact max, then sum) inside the same kernel.
// shift_pred = linear extrapolation of the per-row lse (2*lse_t - lse_{t-1}).
// ---------------------------------------------------------------------------

#define MB     8
#define NB     2048
#define EPSF   1e-3f
#define THRESH 1e-3f
#define NITERS 50
#define CSC    1442.6950408889634f      // log2(e)/eps
#define INVC   6.931471805599453e-4f    // 1/CSC = eps*ln2
#define SMV_MIN 8.077936e-28f           // 2^-90: below this, FTZ mass may matter

#define ROWS   8                         // rows per block (4 f32x2 pairs)
#define PAIRS  (ROWS / 2)
#define WPB    2                         // warps per block (column split)
#define THREADS (WPB * 32)
#define CPW    (NB / WPB)                // 1024 columns per warp
#define TPW    (CPW / 32)                // 32 tile iters per warp
#define RGPB   (NB / ROWS)               // 256 row-groups per batch
#define GRID_HALF (MB * RGPB)            // 2048 blocks

typedef unsigned long long u64;

// Scratch (allocation-free rule: __device__ globals)
__device__ float4   g_cx[MB * NB];  // {x0,x1,x2, c*u - c*||x||^2}
__device__ float4   g_cy[MB * NB];  // {y0,y1,y2, c*v - c*||y||^2}
__device__ float    g_n2x[MB * NB]; // c*||x||^2 (exact, no drift)
__device__ float    g_n2y[MB * NB]; // c*||y||^2
__device__ float    g_shx[MB * NB]; // per-row predicted shift (u-update rows)
__device__ float    g_shy[MB * NB];
__device__ float    g_lsx[MB * NB]; // per-row previous true lse (chain units)
__device__ float    g_lsy[MB * NB];
__device__ float    g_u[MB * NB];
__device__ float    g_v[MB * NB];
__device__ float    g_la[MB * NB];
__device__ float    g_lb[MB * NB];
__device__ unsigned g_err[NITERS];  // per-iter max(err_u, err_v), float bits

__device__ __forceinline__ float ex2f(float x) {
    float r; asm("ex2.approx.ftz.f32 %0, %1;" : "=f"(r) : "f"(x)); return r;
}
__device__ __forceinline__ u64 pack2(float lo, float hi) {
    u64 r; asm("mov.b64 %0, {%1, %2};" : "=l"(r) : "f"(lo), "f"(hi)); return r;
}
__device__ __forceinline__ float lo2(u64 p) {
    float l, h; asm("mov.b64 {%0, %1}, %2;" : "=f"(l), "=f"(h) : "l"(p)); return l;
}
__device__ __forceinline__ float hi2(u64 p) {
    float l, h; asm("mov.b64 {%0, %1}, %2;" : "=f"(l), "=f"(h) : "l"(p)); return h;
}
__device__ __forceinline__ u64 fma2(u64 a, u64 b, u64 c) {
    u64 d; asm("fma.rn.f32x2 %0, %1, %2, %3;" : "=l"(d) : "l"(a), "l"(b), "l"(c)); return d;
}
__device__ __forceinline__ u64 add2(u64 a, u64 b) {
    u64 d; asm("add.rn.f32x2 %0, %1, %2;" : "=l"(d) : "l"(a), "l"(b)); return d;
}

// ---------------------------------------------------------------------------
__global__ void k_init(const float* __restrict__ px, const float* __restrict__ py,
                       const float* __restrict__ a, const float* __restrict__ b,
                       float* __restrict__ out) {
    int i = blockIdx.x * blockDim.x + threadIdx.x;
    if (i < MB * NB) {
        float x0 = px[3 * i], x1 = px[3 * i + 1], x2 = px[3 * i + 2];
        float n2x = CSC * (x0 * x0 + x1 * x1 + x2 * x2);
        g_cx[i] = make_float4(x0, x1, x2, -n2x);     // u = 0
        g_n2x[i] = n2x;
        float y0 = py[3 * i], y1 = py[3 * i + 1], y2 = py[3 * i + 2];
        float n2y = CSC * (y0 * y0 + y1 * y1 + y2 * y2);
        g_cy[i] = make_float4(y0, y1, y2, -n2y);     // v = 0
        g_n2y[i] = n2y;
        g_shx[i] = 0.0f;     // prediction (iter 0 redoes via validity check)
        g_shy[i] = 0.0f;
        g_lsx[i] = 0.0f;
        g_lsy[i] = 0.0f;
        g_u[i] = 0.0f;
        g_v[i] = 0.0f;
        g_la[i] = logf(a[i]);
        g_lb[i] = logf(b[i]);
    }
    if (i < NITERS) g_err[i] = 0u;
    if (i < MB)     out[i] = 0.0f;
}

// ---------------------------------------------------------------------------
// One half Sinkhorn update. SIDE=0 updates u (rows=x, cols=y+v);
//                           SIDE=1 updates v (rows=y, cols=x+u).
// Freeze: once g_err[s] < THRESH, later launches return untouched (slots stay
// 0 < THRESH -> sticky), matching the reference's done flag.
template <int SIDE>
__global__ void __launch_bounds__(THREADS, 14) k_half(int iter) {
    if (iter > 0 && __uint_as_float(g_err[iter - 1]) < THRESH) return;

    __shared__ float s_sm[WPB][ROWS];
    __shared__ float s_mx[WPB][ROWS];

    const int warp  = threadIdx.x >> 5;
    const int lane  = threadIdx.x & 31;
    const int batch = blockIdx.x / RGPB;
    const int row0  = (blockIdx.x % RGPB) * ROWS;
    const int base  = batch * NB;

    const float4* __restrict__ rp  = SIDE ? g_cy : g_cx;   // row-side coords
    const float4* __restrict__ cp  = SIDE ? g_cx : g_cy;   // col-side {coords, qb}
    float4*                    rw  = SIDE ? g_cy : g_cx;   // row-side (finalize .w write)
    const float*  __restrict__ n2  = SIDE ? g_n2y : g_n2x; // c*||row||^2
    float*                     shp = SIDE ? g_shy : g_shx; // predicted shift
    float*                     lsp = SIDE ? g_lsy : g_lsx; // previous lse
    float*                     upd = SIDE ? g_v : g_u;     // potential being updated
    const float*  __restrict__ rl  = SIDE ? g_lb : g_la;   // row-side log marginal

    // Row-pair packed coordinates (pre-scaled by 2c) and packed -shift
    u64 cx2[PAIRS], cy2[PAIRS], cz2[PAIRS], nsh2[PAIRS];
    float sm[ROWS];
#pragma unroll
    for (int p = 0; p < PAIRS; p++) {
        float4 R0 = rp[base + row0 + 2 * p];
        float4 R1 = rp[base + row0 + 2 * p + 1];
        cx2[p] = pack2(R0.x * (2.0f * CSC), R1.x * (2.0f * CSC));
        cy2[p] = pack2(R0.y * (2.0f * CSC), R1.y * (2.0f * CSC));
        cz2[p] = pack2(R0.z * (2.0f * CSC), R1.z * (2.0f * CSC));
        nsh2[p] = pack2(-shp[base + row0 + 2 * p], -shp[base + row0 + 2 * p + 1]);
    }
#pragma unroll
    for (int j = 0; j < ROWS; j++) sm[j] = 0.0f;
    const int kbeg = base + warp * CPW + lane;

    // ---- Fused one-pass: sum of ex2(chain - shift_pred), no max tracking
#pragma unroll 2
    for (int t = 0; t < TPW; t++) {
        int k = kbeg + t * 32;
        float4 C = cp[k];                        // {c0,c1,c2, qb}
        u64 Cx = pack2(C.x, C.x), Cy = pack2(C.y, C.y), Cz = pack2(C.z, C.z);
        u64 Q  = pack2(C.w, C.w);
#pragma unroll
        for (int p = 0; p < PAIRS; p++) {
            u64 s2 = fma2(cx2[p], Cx, fma2(cy2[p], Cy, fma2(cz2[p], Cz, Q)));
            u64 a2 = add2(s2, nsh2[p]);
            sm[2 * p]     += ex2f(lo2(a2));
            sm[2 * p + 1] += ex2f(hi2(a2));
        }
    }
#pragma unroll
    for (int j = 0; j < ROWS; j++) {
#pragma unroll
        for (int o = 16; o; o >>= 1)
            sm[j] += __shfl_xor_sync(0xffffffffu, sm[j], o);
    }
    if (lane == 0) {
#pragma unroll
        for (int j = 0; j < ROWS; j++) s_sm[warp][j] = sm[j];
    }
    __syncthreads();

    // Validity from the sums alone: overflow (inf) or possible FTZ-mass loss
    bool redo = false;
    float smvr[ROWS];
#pragma unroll
    for (int j = 0; j < ROWS; j++) {
        smvr[j] = s_sm[0][j] + s_sm[1][j];
        redo = redo || !(smvr[j] >= SMV_MIN && smvr[j] <= 3.4e38f);
    }

    float amax[ROWS];
#pragma unroll
    for (int j = 0; j < ROWS; j++) amax[j] = 0.0f;

    if (redo) {
        // ---- Corrective two-pass: exact arg-max, then shifted sum
        float mxs[ROWS];
#pragma unroll
        for (int j = 0; j < ROWS; j++) mxs[j] = -3.4e38f;
#pragma unroll 2
        for (int t = 0; t < TPW; t++) {
            int k = kbeg + t * 32;
            float4 C = cp[k];
            u64 Cx = pack2(C.x, C.x), Cy = pack2(C.y, C.y), Cz = pack2(C.z, C.z);
            u64 Q  = pack2(C.w, C.w);
#pragma unroll
            for (int p = 0; p < PAIRS; p++) {
                u64 s2 = fma2(cx2[p], Cx, fma2(cy2[p], Cy, fma2(cz2[p], Cz, Q)));
                u64 a2 = add2(s2, nsh2[p]);
                mxs[2 * p]     = fmaxf(mxs[2 * p],     lo2(a2));
                mxs[2 * p + 1] = fmaxf(mxs[2 * p + 1], hi2(a2));
            }
        }
#pragma unroll
        for (int j = 0; j < ROWS; j++) {
#pragma unroll
            for (int o = 16; o; o >>= 1)
                mxs[j] = fmaxf(mxs[j], __shfl_xor_sync(0xffffffffu, mxs[j], o));
        }
        if (lane == 0) {
#pragma unroll
            for (int j = 0; j < ROWS; j++) s_mx[warp][j] = mxs[j];
        }
        __syncthreads();
        u64 nmx2[PAIRS];
#pragma unroll
        for (int j = 0; j < ROWS; j++)
            amax[j] = fmaxf(s_mx[0][j], s_mx[1][j]);
#pragma unroll
        for (int p = 0; p < PAIRS; p++)
            nmx2[p] = add2(nsh2[p], pack2(-amax[2 * p], -amax[2 * p + 1]));
#pragma unroll
        for (int j = 0; j < ROWS; j++) sm[j] = 0.0f;
#pragma unroll 2
        for (int t = 0; t < TPW; t++) {
            int k = kbeg + t * 32;
            float4 C = cp[k];
            u64 Cx = pack2(C.x, C.x), Cy = pack2(C.y, C.y), Cz = pack2(C.z, C.z);
            u64 Q  = pack2(C.w, C.w);
#pragma unroll
            for (int p = 0; p < PAIRS; p++) {
                u64 s2 = fma2(cx2[p], Cx, fma2(cy2[p], Cy, fma2(cz2[p], Cz, Q)));
                u64 a2 = add2(s2, nmx2[p]);
                sm[2 * p]     += ex2f(lo2(a2));
                sm[2 * p + 1] += ex2f(hi2(a2));
            }
        }
#pragma unroll
        for (int j = 0; j < ROWS; j++) {
#pragma unroll
            for (int o = 16; o; o >>= 1)
                sm[j] += __shfl_xor_sync(0xffffffffu, sm[j], o);
        }
        if (lane == 0) {
#pragma unroll
            for (int j = 0; j < ROWS; j++) s_sm[warp][j] = sm[j];
        }
        __syncthreads();
    }

    // ---- Finalize: warp 0, lanes 0..7 each own one row
    if (warp == 0 && lane < ROWS) {
        int r = base + row0 + lane;
        float smv = redo ? (s_sm[0][lane] + s_sm[1][lane]) : smvr[lane];
        float lse = shp[r] + amax[lane] + __log2f(smv);  // true chain lse (amax=0 if !redo)
        float n2r = n2[r];                               // c*||row||^2 (exact)
        float nv = fmaf(n2r - lse, INVC, EPSF * rl[r]);
        float ov = upd[r];
        upd[r] = nv;
        // shift prediction for this row's NEXT same-side iteration
        float lse_old = lsp[r];
        lsp[r] = lse;
        shp[r] = (iter == 0) ? lse : (lse + (lse - lse_old));
        // refresh this row's column-side qb: c*pot_new - c*||row||^2
        ((float*)(rw + r))[3] = fmaf(CSC, nv, -n2r);
        float e = fabsf(nv - ov);
#pragma unroll
        for (int o = 4; o; o >>= 1)
            e = fmaxf(e, __shfl_xor_sync(0x000000ffu, e, o));
        if (lane == 0)
            atomicMax(&g_err[iter], __float_as_uint(e)); // e>=0: uint order==float order
    }
}

// ---------------------------------------------------------------------------
// loss[b] = sum_{i,k} M * exp((u_i + v_k - M)/eps)
__global__ void __launch_bounds__(THREADS, 14) k_loss(float* __restrict__ out) {
    const int warp  = threadIdx.x >> 5;
    const int lane  = threadIdx.x & 31;
    const int batch = blockIdx.x / RGPB;
    const int row0  = (blockIdx.x % RGPB) * ROWS;
    const int base  = batch * NB;

    float cx[ROWS], cy[ROWS], cz[ROWS], aj[ROWS], U[ROWS];
#pragma unroll
    for (int j = 0; j < ROWS; j++) {
        float4 R = g_cx[base + row0 + j];            // {x, c*u - c*x2}
        cx[j] = R.x * (2.0f * CSC);
        cy[j] = R.y * (2.0f * CSC);
        cz[j] = R.z * (2.0f * CSC);
        aj[j] = R.w;
        U[j]  = g_u[base + row0 + j];
    }
    const int kbeg = base + warp * CPW + lane;

    float tot = 0.0f;
#pragma unroll 2
    for (int t = 0; t < TPW; t++) {
        int k = kbeg + t * 32;
        float4 C = g_cy[k];                          // {y, c*v - c*y2}
        float vk = g_v[k];
#pragma unroll
        for (int j = 0; j < ROWS; j++) {
            float carg = fmaf(cx[j], C.x, fmaf(cy[j], C.y, fmaf(cz[j], C.z, C.w + aj[j])));
            float e  = ex2f(carg);
            float uv = U[j] + vk;
            float Mv = fmaf(carg, -INVC, uv);        // = M (unclamped)
            tot = fmaf(Mv, e, tot);
        }
    }
#pragma unroll
    for (int o = 16; o; o >>= 1)
        tot += __shfl_xor_sync(0xffffffffu, tot, o);
    if (lane == 0) atomicAdd(&out[batch], tot);
}

// ---------------------------------------------------------------------------
extern "C" void kernel_launch(void* const* d_in, const int* in_sizes, int n_in,
                              void* d_out, int out_size) {
    (void)in_sizes; (void)n_in; (void)out_size;
    const float* px = (const float*)d_in[0];   // predicted [8,2048,3]
    const float* py = (const float*)d_in[1];   // expected  [8,2048,3]
    const float* a  = (const float*)d_in[2];   // [8,2048]
    const float* b  = (const float*)d_in[3];   // [8,2048]
    float* out = (float*)d_out;                // [8]

    k_init<<<(MB * NB + 255) / 256, 256>>>(px, py, a, b, out);
    for (int t = 0; t < NITERS; t++) {
        k_half<0><<<GRID_HALF, THREADS>>>(t);
        k_half<1><<<GRID_HALF, THREADS>>>(t);
    }
    k_loss<<<GRID_HALF, THREADS>>>(out);
}

// round 13
// speedup vs baseline: 2.9978x; 1.0652x over previous
#include <cuda_runtime.h>
#include <math.h>

// ---------------------------------------------------------------------------
// SinkhornLoss: m=8, n=2048, d=3, eps=1e-3, 50 iters, early-stop flag.
// chain(i,k) = 2c*x_i.y_k + qb_k, qb_k = c*pot_k - c*||col_k||^2, c=log2e/eps.
// R12: one-pass LSE (R11) + PER-TILE EXP SKIPPING: a tile whose every
// arg = chain - shift is < -60 contributes < 2^-49 and skips all 8 ex2+adds
// (warp vote). Validity window tightened to smv >= 2^-30 so dropped mass is
// <= 2^-19 relative. Redo path (exact max, smv >= 1) uses the same skip.
// ---------------------------------------------------------------------------

#define MB     8
#define NB     2048
#define EPSF   1e-3f
#define THRESH 1e-3f
#define NITERS 50
#define CSC    1442.6950408889634f      // log2(e)/eps
#define INVC   6.931471805599453e-4f    // 1/CSC = eps*ln2
#define SMV_MIN 9.3132257e-10f          // 2^-30: validity floor for one-pass sum
#define SKIPT  (-60.0f)                 // per-tile skip threshold (log2 units)

#define ROWS   8                         // rows per block (4 f32x2 pairs)
#define PAIRS  (ROWS / 2)
#define WPB    2                         // warps per block (column split)
#define THREADS (WPB * 32)
#define CPW    (NB / WPB)                // 1024 columns per warp
#define TPW    (CPW / 32)                // 32 tile iters per warp
#define RGPB   (NB / ROWS)               // 256 row-groups per batch
#define GRID_HALF (MB * RGPB)            // 2048 blocks

typedef unsigned long long u64;

// Scratch (allocation-free rule: __device__ globals)
__device__ float4   g_cx[MB * NB];  // {x0,x1,x2, c*u - c*||x||^2}
__device__ float4   g_cy[MB * NB];  // {y0,y1,y2, c*v - c*||y||^2}
__device__ float    g_n2x[MB * NB]; // c*||x||^2 (exact, no drift)
__device__ float    g_n2y[MB * NB]; // c*||y||^2
__device__ float    g_shx[MB * NB]; // per-row predicted shift (u-update rows)
__device__ float    g_shy[MB * NB];
__device__ float    g_lsx[MB * NB]; // per-row previous true lse (chain units)
__device__ float    g_lsy[MB * NB];
__device__ float    g_u[MB * NB];
__device__ float    g_v[MB * NB];
__device__ float    g_la[MB * NB];
__device__ float    g_lb[MB * NB];
__device__ unsigned g_err[NITERS];  // per-iter max(err_u, err_v), float bits

__device__ __forceinline__ float ex2f(float x) {
    float r; asm("ex2.approx.ftz.f32 %0, %1;" : "=f"(r) : "f"(x)); return r;
}
__device__ __forceinline__ u64 pack2(float lo, float hi) {
    u64 r; asm("mov.b64 %0, {%1, %2};" : "=l"(r) : "f"(lo), "f"(hi)); return r;
}
__device__ __forceinline__ float lo2(u64 p) {
    float l, h; asm("mov.b64 {%0, %1}, %2;" : "=f"(l), "=f"(h) : "l"(p)); return l;
}
__device__ __forceinline__ float hi2(u64 p) {
    float l, h; asm("mov.b64 {%0, %1}, %2;" : "=f"(l), "=f"(h) : "l"(p)); return h;
}
__device__ __forceinline__ u64 fma2(u64 a, u64 b, u64 c) {
    u64 d; asm("fma.rn.f32x2 %0, %1, %2, %3;" : "=l"(d) : "l"(a), "l"(b), "l"(c)); return d;
}
__device__ __forceinline__ u64 add2(u64 a, u64 b) {
    u64 d; asm("add.rn.f32x2 %0, %1, %2;" : "=l"(d) : "l"(a), "l"(b)); return d;
}

// ---------------------------------------------------------------------------
__global__ void k_init(const float* __restrict__ px, const float* __restrict__ py,
                       const float* __restrict__ a, const float* __restrict__ b,
                       float* __restrict__ out) {
    int i = blockIdx.x * blockDim.x + threadIdx.x;
    if (i < MB * NB) {
        float x0 = px[3 * i], x1 = px[3 * i + 1], x2 = px[3 * i + 2];
        float n2x = CSC * (x0 * x0 + x1 * x1 + x2 * x2);
        g_cx[i] = make_float4(x0, x1, x2, -n2x);     // u = 0
        g_n2x[i] = n2x;
        float y0 = py[3 * i], y1 = py[3 * i + 1], y2 = py[3 * i + 2];
        float n2y = CSC * (y0 * y0 + y1 * y1 + y2 * y2);
        g_cy[i] = make_float4(y0, y1, y2, -n2y);     // v = 0
        g_n2y[i] = n2y;
        g_shx[i] = 0.0f;     // prediction (iter 0 redoes via validity check)
        g_shy[i] = 0.0f;
        g_lsx[i] = 0.0f;
        g_lsy[i] = 0.0f;
        g_u[i] = 0.0f;
        g_v[i] = 0.0f;
        g_la[i] = logf(a[i]);
        g_lb[i] = logf(b[i]);
    }
    if (i < NITERS) g_err[i] = 0u;
    if (i < MB)     out[i] = 0.0f;
}

// ---------------------------------------------------------------------------
// One half Sinkhorn update. SIDE=0 updates u (rows=x, cols=y+v);
//                           SIDE=1 updates v (rows=y, cols=x+u).
// Freeze: once g_err[s] < THRESH, later launches return untouched (slots stay
// 0 < THRESH -> sticky), matching the reference's done flag.
template <int SIDE>
__global__ void __launch_bounds__(THREADS, 13) k_half(int iter) {
    if (iter > 0 && __uint_as_float(g_err[iter - 1]) < THRESH) return;

    __shared__ float s_sm[WPB][ROWS];
    __shared__ float s_mx[WPB][ROWS];

    const int warp  = threadIdx.x >> 5;
    const int lane  = threadIdx.x & 31;
    const int batch = blockIdx.x / RGPB;
    const int row0  = (blockIdx.x % RGPB) * ROWS;
    const int base  = batch * NB;

    const float4* __restrict__ rp  = SIDE ? g_cy : g_cx;   // row-side coords
    const float4* __restrict__ cp  = SIDE ? g_cx : g_cy;   // col-side {coords, qb}
    float4*                    rw  = SIDE ? g_cy : g_cx;   // row-side (finalize .w write)
    const float*  __restrict__ n2  = SIDE ? g_n2y : g_n2x; // c*||row||^2
    float*                     shp = SIDE ? g_shy : g_shx; // predicted shift
    float*                     lsp = SIDE ? g_lsy : g_lsx; // previous lse
    float*                     upd = SIDE ? g_v : g_u;     // potential being updated
    const float*  __restrict__ rl  = SIDE ? g_lb : g_la;   // row-side log marginal

    // Row-pair packed coordinates (pre-scaled by 2c) and packed -shift
    u64 cx2[PAIRS], cy2[PAIRS], cz2[PAIRS], nsh2[PAIRS];
    float sm[ROWS];
#pragma unroll
    for (int p = 0; p < PAIRS; p++) {
        float4 R0 = rp[base + row0 + 2 * p];
        float4 R1 = rp[base + row0 + 2 * p + 1];
        cx2[p] = pack2(R0.x * (2.0f * CSC), R1.x * (2.0f * CSC));
        cy2[p] = pack2(R0.y * (2.0f * CSC), R1.y * (2.0f * CSC));
        cz2[p] = pack2(R0.z * (2.0f * CSC), R1.z * (2.0f * CSC));
        nsh2[p] = pack2(-shp[base + row0 + 2 * p], -shp[base + row0 + 2 * p + 1]);
    }
#pragma unroll
    for (int j = 0; j < ROWS; j++) sm[j] = 0.0f;
    const int kbeg = base + warp * CPW + lane;

    // ---- Fused one-pass: sum of ex2(chain - shift_pred), tile-skip when the
    // whole warp's args are < SKIPT (contribution < 2^-49; window makes it
    // <= 2^-19 relative).
#pragma unroll 2
    for (int t = 0; t < TPW; t++) {
        int k = kbeg + t * 32;
        float4 C = cp[k];                        // {c0,c1,c2, qb}
        u64 Cx = pack2(C.x, C.x), Cy = pack2(C.y, C.y), Cz = pack2(C.z, C.z);
        u64 Q  = pack2(C.w, C.w);
        u64 a2[PAIRS];
        float mx = -3.4e38f;
#pragma unroll
        for (int p = 0; p < PAIRS; p++) {
            u64 s2 = fma2(cx2[p], Cx, fma2(cy2[p], Cy, fma2(cz2[p], Cz, Q)));
            a2[p] = add2(s2, nsh2[p]);
            mx = fmaxf(mx, fmaxf(lo2(a2[p]), hi2(a2[p])));
        }
        if (__any_sync(0xffffffffu, mx > SKIPT)) {
#pragma unroll
            for (int p = 0; p < PAIRS; p++) {
                sm[2 * p]     += ex2f(lo2(a2[p]));
                sm[2 * p + 1] += ex2f(hi2(a2[p]));
            }
        }
    }
#pragma unroll
    for (int j = 0; j < ROWS; j++) {
#pragma unroll
        for (int o = 16; o; o >>= 1)
            sm[j] += __shfl_xor_sync(0xffffffffu, sm[j], o);
    }
    if (lane == 0) {
#pragma unroll
        for (int j = 0; j < ROWS; j++) s_sm[warp][j] = sm[j];
    }
    __syncthreads();

    // Validity from the sums alone: prediction within [-30, +127] log2 units
    bool redo = false;
    float smvr[ROWS];
#pragma unroll
    for (int j = 0; j < ROWS; j++) {
        smvr[j] = s_sm[0][j] + s_sm[1][j];
        redo = redo || !(smvr[j] >= SMV_MIN && smvr[j] <= 3.4e38f);
    }

    float amax[ROWS];
#pragma unroll
    for (int j = 0; j < ROWS; j++) amax[j] = 0.0f;

    if (redo) {
        // ---- Corrective two-pass: exact arg-max, then shifted (skipped) sum
        float mxs[ROWS];
#pragma unroll
        for (int j = 0; j < ROWS; j++) mxs[j] = -3.4e38f;
#pragma unroll 2
        for (int t = 0; t < TPW; t++) {
            int k = kbeg + t * 32;
            float4 C = cp[k];
            u64 Cx = pack2(C.x, C.x), Cy = pack2(C.y, C.y), Cz = pack2(C.z, C.z);
            u64 Q  = pack2(C.w, C.w);
#pragma unroll
            for (int p = 0; p < PAIRS; p++) {
                u64 s2 = fma2(cx2[p], Cx, fma2(cy2[p], Cy, fma2(cz2[p], Cz, Q)));
                u64 a2 = add2(s2, nsh2[p]);
                mxs[2 * p]     = fmaxf(mxs[2 * p],     lo2(a2));
                mxs[2 * p + 1] = fmaxf(mxs[2 * p + 1], hi2(a2));
            }
        }
#pragma unroll
        for (int j = 0; j < ROWS; j++) {
#pragma unroll
            for (int o = 16; o; o >>= 1)
                mxs[j] = fmaxf(mxs[j], __shfl_xor_sync(0xffffffffu, mxs[j], o));
        }
        if (lane == 0) {
#pragma unroll
            for (int j = 0; j < ROWS; j++) s_mx[warp][j] = mxs[j];
        }
        __syncthreads();
        u64 nmx2[PAIRS];
#pragma unroll
        for (int j = 0; j < ROWS; j++)
            amax[j] = fmaxf(s_mx[0][j], s_mx[1][j]);
#pragma unroll
        for (int p = 0; p < PAIRS; p++)
            nmx2[p] = add2(nsh2[p], pack2(-amax[2 * p], -amax[2 * p + 1]));
#pragma unroll
        for (int j = 0; j < ROWS; j++) sm[j] = 0.0f;
#pragma unroll 2
        for (int t = 0; t < TPW; t++) {
            int k = kbeg + t * 32;
            float4 C = cp[k];
            u64 Cx = pack2(C.x, C.x), Cy = pack2(C.y, C.y), Cz = pack2(C.z, C.z);
            u64 Q  = pack2(C.w, C.w);
            u64 a2[PAIRS];
            float mx = -3.4e38f;
#pragma unroll
            for (int p = 0; p < PAIRS; p++) {
                u64 s2 = fma2(cx2[p], Cx, fma2(cy2[p], Cy, fma2(cz2[p], Cz, Q)));
                a2[p] = add2(s2, nmx2[p]);
                mx = fmaxf(mx, fmaxf(lo2(a2[p]), hi2(a2[p])));
            }
            if (__any_sync(0xffffffffu, mx > SKIPT)) {   // exact max: smv>=1, drop<=2^-49
#pragma unroll
                for (int p = 0; p < PAIRS; p++) {
                    sm[2 * p]     += ex2f(lo2(a2[p]));
                    sm[2 * p + 1] += ex2f(hi2(a2[p]));
                }
            }
        }
#pragma unroll
        for (int j = 0; j < ROWS; j++) {
#pragma unroll
            for (int o = 16; o; o >>= 1)
                sm[j] += __shfl_xor_sync(0xffffffffu, sm[j], o);
        }
        if (lane == 0) {
#pragma unroll
            for (int j = 0; j < ROWS; j++) s_sm[warp][j] = sm[j];
        }
        __syncthreads();
    }

    // ---- Finalize: warp 0, lanes 0..7 each own one row
    if (warp == 0 && lane < ROWS) {
        int r = base + row0 + lane;
        float smv = redo ? (s_sm[0][lane] + s_sm[1][lane]) : smvr[lane];
        float lse = shp[r] + amax[lane] + __log2f(smv);  // true chain lse (amax=0 if !redo)
        float n2r = n2[r];                               // c*||row||^2 (exact)
        float nv = fmaf(n2r - lse, INVC, EPSF * rl[r]);
        float ov = upd[r];
        upd[r] = nv;
        // shift prediction for this row's NEXT same-side iteration
        float lse_old = lsp[r];
        lsp[r] = lse;
        shp[r] = (iter == 0) ? lse : (lse + (lse - lse_old));
        // refresh this row's column-side qb: c*pot_new - c*||row||^2
        ((float*)(rw + r))[3] = fmaf(CSC, nv, -n2r);
        float e = fabsf(nv - ov);
#pragma unroll
        for (int o = 4; o; o >>= 1)
            e = fmaxf(e, __shfl_xor_sync(0x000000ffu, e, o));
        if (lane == 0)
            atomicMax(&g_err[iter], __float_as_uint(e)); // e>=0: uint order==float order
    }
}

// ---------------------------------------------------------------------------
// loss[b] = sum_{i,k} M * exp((u_i + v_k - M)/eps)  with the same tile skip
__global__ void __launch_bounds__(THREADS, 13) k_loss(float* __restrict__ out) {
    const int warp  = threadIdx.x >> 5;
    const int lane  = threadIdx.x & 31;
    const int batch = blockIdx.x / RGPB;
    const int row0  = (blockIdx.x % RGPB) * ROWS;
    const int base  = batch * NB;

    float cx[ROWS], cy[ROWS], cz[ROWS], aj[ROWS], U[ROWS];
#pragma unroll
    for (int j = 0; j < ROWS; j++) {
        float4 R = g_cx[base + row0 + j];            // {x, c*u - c*x2}
        cx[j] = R.x * (2.0f * CSC);
        cy[j] = R.y * (2.0f * CSC);
        cz[j] = R.z * (2.0f * CSC);
        aj[j] = R.w;
        U[j]  = g_u[base + row0 + j];
    }
    const int kbeg = base + warp * CPW + lane;

    float tot = 0.0f;
#pragma unroll 2
    for (int t = 0; t < TPW; t++) {
        int k = kbeg + t * 32;
        float4 C = g_cy[k];                          // {y, c*v - c*y2}
        float vk = g_v[k];
        float carg[ROWS];
        float mx = -3.4e38f;
#pragma unroll
        for (int j = 0; j < ROWS; j++) {
            carg[j] = fmaf(cx[j], C.x, fmaf(cy[j], C.y, fmaf(cz[j], C.z, C.w + aj[j])));
            mx = fmaxf(mx, carg[j]);
        }
        if (__any_sync(0xffffffffu, mx > SKIPT)) {
#pragma unroll
            for (int j = 0; j < ROWS; j++) {
                float e  = ex2f(carg[j]);
                float uv = U[j] + vk;
                float Mv = fmaf(carg[j], -INVC, uv); // = M (unclamped)
                tot = fmaf(Mv, e, tot);
            }
        }
    }
#pragma unroll
    for (int o = 16; o; o >>= 1)
        tot += __shfl_xor_sync(0xffffffffu, tot, o);
    if (lane == 0) atomicAdd(&out[batch], tot);
}

// ---------------------------------------------------------------------------
extern "C" void kernel_launch(void* const* d_in, const int* in_sizes, int n_in,
                              void* d_out, int out_size) {
    (void)in_sizes; (void)n_in; (void)out_size;
    const float* px = (const float*)d_in[0];   // predicted [8,2048,3]
    const float* py = (const float*)d_in[1];   // expected  [8,2048,3]
    const float* a  = (const float*)d_in[2];   // [8,2048]
    const float* b  = (const float*)d_in[3];   // [8,2048]
    float* out = (float*)d_out;                // [8]

    k_init<<<(MB * NB + 255) / 256, 256>>>(px, py, a, b, out);
    for (int t = 0; t < NITERS; t++) {
        k_half<0><<<GRID_HALF, THREADS>>>(t);
        k_half<1><<<GRID_HALF, THREADS>>>(t);
    }
    k_loss<<<GRID_HALF, THREADS>>>(out);
}